// round 16
// baseline (speedup 1.0000x reference)
#include <cuda_runtime.h>
#include <math.h>

#define NCH 16
#define NB 5
#define MAXN 20000
#define MAXE 640000
#define MAXE_PAD (MAXE + 3 * MAXN + 16)   // padded segments + prefetch slack

// Scratch (allocation-free: __device__ globals; zero-initialized at module load)
__device__ int g_counts[MAXN];
__device__ int g_row[MAXN + 1];
__device__ int g_rank[MAXE];
__device__ float4 g_rec[MAXE_PAD];        // sorted+padded: {ex, ey, ez, sender_bits}
__device__ float4 g_pack[MAXN * NCH];     // {n1x, n1y, n1z, n0v} per (node, channel)

// One wide pass: histogram+rank atomics, node-feature packing, coords copy.
// Requires g_counts == 0 on entry (true at load; k_scatter re-zeroes each call).
__global__ void k_hist(const int* __restrict__ recv, int E,
                       const float* __restrict__ nodes0,
                       const float* __restrict__ nodes1, int npack,
                       const float* __restrict__ coords, float* __restrict__ outc,
                       int ncoord) {
    int i = blockIdx.x * blockDim.x + threadIdx.x;
    if (i < E) g_rank[i] = atomicAdd(&g_counts[recv[i]], 1);
    if (i < npack)
        g_pack[i] = make_float4(nodes1[3 * i], nodes1[3 * i + 1],
                                nodes1[3 * i + 2], nodes0[i]);
    if (i < ncoord) outc[i] = coords[i];
}

// Single-block scan over PADDED counts (rounded up to multiple of 4).
__global__ void k_scan(int n) {
    const int T = 1024;
    const int ITEMS = 20;
    int tid = threadIdx.x;
    int lane = tid & 31, wid = tid >> 5;
    int start = tid * ITEMS;

    int loc[ITEMS];
    int sum = 0;
    #pragma unroll
    for (int k = 0; k < ITEMS; k++) {
        int i = start + k;
        int v = (i < n) ? g_counts[i] : 0;
        loc[k] = sum;
        sum += (v + 3) & ~3;              // padded size
    }
    int s = sum;
    #pragma unroll
    for (int off = 1; off < 32; off <<= 1) {
        int t = __shfl_up_sync(0xffffffffu, s, off);
        if (lane >= off) s += t;
    }
    __shared__ int wsum[32];
    if (lane == 31) wsum[wid] = s;
    __syncthreads();
    if (wid == 0) {
        int w = wsum[lane];
        #pragma unroll
        for (int off = 1; off < 32; off <<= 1) {
            int t = __shfl_up_sync(0xffffffffu, w, off);
            if (lane >= off) w += t;
        }
        wsum[lane] = w;
    }
    __syncthreads();
    int base = (wid > 0 ? wsum[wid - 1] : 0) + (s - sum);
    #pragma unroll
    for (int k = 0; k < ITEMS; k++) {
        int i = start + k;
        if (i < n) g_row[i] = base + loc[k];
    }
    if (tid == T - 1) g_row[n] = wsum[31];
}

// Scatter + pad fill. Threads [0,E): one scattered 16B store per edge.
// Threads [E, E+n_nodes): fill node pad slots with the zero-contribution
// dummy record (r=40 -> all rbfs == 0) and re-zero g_counts for next call.
__global__ void k_scatter(const int* __restrict__ recv,
                          const int* __restrict__ senders,
                          const float* __restrict__ edges, int E, int n_nodes) {
    int i = blockIdx.x * blockDim.x + threadIdx.x;
    if (i < E) {
        int pos = g_row[recv[i]] + g_rank[i];
        float ex = edges[3 * i + 0];
        float ey = edges[3 * i + 1];
        float ez = edges[3 * i + 2];
        g_rec[pos] = make_float4(ex, ey, ez, __int_as_float(senders[i]));
    } else {
        int j = i - E;
        if (j < n_nodes) {
            int v = g_counts[j];
            g_counts[j] = 0;
            int rowstart = g_row[j];
            int vp = (v + 3) & ~3;
            const float4 DUMMY = make_float4(40.0f, 0.0f, 0.0f, 0.0f);
            for (int d = v; d < vp; d++) g_rec[rowstart + d] = DUMMY;
        }
    }
}

// Radial + tensor-product body for one edge (always unguarded).
#define EDGE_BODY(rec, n0v, n1x, n1y, n1z)                                     \
{                                                                              \
    float ex = (rec).x, ey = (rec).y, ez = (rec).z;                            \
    float r2 = fmaf(ex, ex, fmaf(ey, ey, ez * ez));                            \
    float r  = sqrtf(r2);                                                      \
    float E0 = __expf(-0.7f * r2);                                             \
    float tt = __expf(1.225f * r);                                             \
    float q1 = E0 * tt, q2 = q1 * tt, q3 = q2 * tt, q4 = q3 * tt;              \
    float rad00 = fmaf(q4, a00[4], fmaf(q3, a00[3], fmaf(q2, a00[2], fmaf(q1, a00[1], E0 * a00[0])))); \
    float rad01 = fmaf(q4, a01[4], fmaf(q3, a01[3], fmaf(q2, a01[2], fmaf(q1, a01[1], E0 * a01[0])))); \
    float rad10 = fmaf(q4, a10[4], fmaf(q3, a10[3], fmaf(q2, a10[2], fmaf(q1, a10[1], E0 * a10[0])))); \
    float rad11 = fmaf(q4, a11[4], fmaf(q3, a11[3], fmaf(q2, a11[2], fmaf(q1, a11[1], E0 * a11[0])))); \
    m0a = fmaf(n0v, rad00, m0a);                                               \
    float dot11 = fmaf(n1x, ey, fmaf(n1y, ez, n1z * ex));                      \
    m0b = fmaf(W110f * rad11, dot11, m0b);                                     \
    float t01 = (n0v) * rad01;                                                 \
    m1a0 = fmaf(t01, ey, m1a0);                                                \
    m1a1 = fmaf(t01, ez, m1a1);                                                \
    m1a2 = fmaf(t01, ex, m1a2);                                                \
    m1b0 = fmaf(rad10, n1x, m1b0);                                             \
    m1b1 = fmaf(rad10, n1y, m1b1);                                             \
    m1b2 = fmaf(rad10, n1z, m1b2);                                             \
    float t11 = W111f * rad11;                                                 \
    m1c0 = fmaf(t11, (n1y) * ex - (n1z) * ez, m1c0);                           \
    m1c1 = fmaf(t11, (n1z) * ey - (n1x) * ex, m1c1);                           \
    m1c2 = fmaf(t11, (n1x) * ez - (n1y) * ey, m1c2);                           \
}

// Main gather: grid-stride NODE loop per warp; padded segments (no guards).
// Two-stream software pipeline: rec loads prefetched at iteration top,
// pack loads prefetched at iteration BOTTOM (one full iteration of cover).
__global__ void __launch_bounds__(128, 8) k_main(
    const float* __restrict__ c00, const float* __restrict__ c01,
    const float* __restrict__ c10, const float* __restrict__ c11,
    const float* __restrict__ w000, const float* __restrict__ w011,
    const float* __restrict__ w101, const float* __restrict__ w110,
    const float* __restrict__ w111,
    float* __restrict__ out0, float* __restrict__ out1, int n_nodes)
{
    int gwarp = (blockIdx.x * blockDim.x + threadIdx.x) >> 5;
    int nwarps = (gridDim.x * blockDim.x) >> 5;
    int lane = threadIdx.x & 31;
    int c = lane & 15;
    int half = lane >> 4;

    const float Kf[NB] = {
        1.0f,
        (float)exp(-0.7 * 0.875 * 0.875),
        (float)exp(-0.7 * 1.75  * 1.75),
        (float)exp(-0.7 * 2.625 * 2.625),
        (float)exp(-0.7 * 3.5   * 3.5)
    };
    const float Y00 = 0.28209479177387814f;
    const float Y1C = 0.4886025119029199f;
    float W000f = w000[c] * Y00;
    float W011f = w011[c] * Y1C;
    float W101f = w101[c] * Y00;
    float W110f = w110[c] * 0.57735026918962576f * Y1C;  // 1/sqrt(3) * Y1C
    float W111f = w111[c] * 0.70710678118654752f * Y1C;  // 1/sqrt(2) * Y1C

    float a00[NB], a01[NB], a10[NB], a11[NB];
    #pragma unroll
    for (int k = 0; k < NB; k++) {
        a00[k] = c00[c * NB + k] * Kf[k] * W000f;   // rad00 pre-weighted
        a01[k] = c01[c * NB + k] * Kf[k] * W011f;   // rad01 pre-weighted
        a10[k] = c10[c * NB + k] * Kf[k] * W101f;   // rad10 pre-weighted
        a11[k] = c11[c * NB + k] * Kf[k];           // rad11 raw (two weights)
    }

    for (int node = gwarp; node < n_nodes; node += nwarps) {
        int rs = g_row[node];
        int re = g_row[node + 1];      // padded: (re - rs) % 4 == 0

        float m0a = 0.f, m0b = 0.f;
        float m1a0 = 0.f, m1a1 = 0.f, m1a2 = 0.f;
        float m1b0 = 0.f, m1b1 = 0.f, m1b2 = 0.f;
        float m1c0 = 0.f, m1c1 = 0.f, m1c2 = 0.f;

        if (rs < re) {
            // Prologue: first recs, then first packs (one-time serial cost).
            float4 rec0 = g_rec[rs + half];
            float4 rec1 = g_rec[rs + 2 + half];
            float4 pk0 = g_pack[__float_as_int(rec0.w) * NCH + c];
            float4 pk1 = g_pack[__float_as_int(rec1.w) * NCH + c];

            #pragma unroll 1
            for (int base = rs; base < re; base += 4) {
                // Prefetch NEXT group's recs (may overrun into slack — fine).
                float4 nrec0 = g_rec[base + 4 + half];
                float4 nrec1 = g_rec[base + 6 + half];

                // Compute with CURRENT recs + packs (loaded last iteration).
                EDGE_BODY(rec0, pk0.w, pk0.x, pk0.y, pk0.z);
                EDGE_BODY(rec1, pk1.w, pk1.x, pk1.y, pk1.z);

                // Rotate and prefetch NEXT packs — nrec had both EDGE_BODYs
                // to arrive; pk gets a full iteration of cover before use.
                rec0 = nrec0; rec1 = nrec1;
                pk0 = g_pack[__float_as_int(rec0.w) * NCH + c];
                pk1 = g_pack[__float_as_int(rec1.w) * NCH + c];
            }
        }

        // Combine the two half-warps and store this node's outputs.
        const unsigned FULL = 0xffffffffu;
        m0a  += __shfl_xor_sync(FULL, m0a, 16);
        m0b  += __shfl_xor_sync(FULL, m0b, 16);
        m1a0 += __shfl_xor_sync(FULL, m1a0, 16);
        m1a1 += __shfl_xor_sync(FULL, m1a1, 16);
        m1a2 += __shfl_xor_sync(FULL, m1a2, 16);
        m1b0 += __shfl_xor_sync(FULL, m1b0, 16);
        m1b1 += __shfl_xor_sync(FULL, m1b1, 16);
        m1b2 += __shfl_xor_sync(FULL, m1b2, 16);
        m1c0 += __shfl_xor_sync(FULL, m1c0, 16);
        m1c1 += __shfl_xor_sync(FULL, m1c1, 16);
        m1c2 += __shfl_xor_sync(FULL, m1c2, 16);

        if (half == 0) {
            out0[node * 32 + c]      = m0a;
            out0[node * 32 + 16 + c] = m0b;
            float* oa = out1 + (node * 48 + c) * 3;
            oa[0] = m1a0; oa[1] = m1a1; oa[2] = m1a2;
            float* ob = out1 + (node * 48 + 16 + c) * 3;
            ob[0] = m1b0; ob[1] = m1b1; ob[2] = m1b2;
            float* oc = out1 + (node * 48 + 32 + c) * 3;
            oc[0] = m1c0; oc[1] = m1c1; oc[2] = m1c2;
        }
    }
}

extern "C" void kernel_launch(void* const* d_in, const int* in_sizes, int n_in,
                              void* d_out, int out_size) {
    const float* coords  = (const float*)d_in[0];
    const float* nodes0  = (const float*)d_in[1];
    const float* nodes1  = (const float*)d_in[2];
    const float* edges   = (const float*)d_in[3];
    const int*   senders = (const int*)d_in[4];
    const int*   recv    = (const int*)d_in[5];
    const float* c00 = (const float*)d_in[6];
    const float* c01 = (const float*)d_in[7];
    const float* c10 = (const float*)d_in[8];
    const float* c11 = (const float*)d_in[9];
    const float* w000 = (const float*)d_in[10];
    const float* w011 = (const float*)d_in[11];
    const float* w101 = (const float*)d_in[12];
    const float* w110 = (const float*)d_in[13];
    const float* w111 = (const float*)d_in[14];
    float* out = (float*)d_out;

    int N = in_sizes[0] / 3;
    int E = in_sizes[3] / 3;

    float* out0 = out + (size_t)3 * N;
    float* out1 = out0 + (size_t)32 * N;

    // hist + node packing + coords copy fused.
    k_hist<<<(E + 255) / 256, 256>>>(recv, E, nodes0, nodes1, N * NCH,
                                     coords, out, 3 * N);
    k_scan<<<1, 1024>>>(N);
    // scatter + pad fill (E edge threads + N fill threads).
    k_scatter<<<(E + N + 255) / 256, 256>>>(recv, senders, edges, E, N);
    // 1184 blocks x 4 warps = 4736 warps; 8 small blocks/SM smooth the tail.
    k_main<<<1184, 128>>>(c00, c01, c10, c11,
                          w000, w011, w101, w110, w111,
                          out0, out1, N);
}

// round 17
// speedup vs baseline: 1.0428x; 1.0428x over previous
#include <cuda_runtime.h>
#include <math.h>

#define NCH 16
#define NB 5
#define MAXN 20000
#define MAXE 640000
#define MAXE_PAD (MAXE + 3 * MAXN + 16)   // padded segments + prefetch slack

// Scratch (allocation-free: __device__ globals; zero-initialized at module load)
__device__ int g_counts[MAXN];
__device__ int g_row[MAXN + 1];
__device__ int g_rank[MAXE];
__device__ float4 g_rec[MAXE_PAD];        // sorted+padded: {ex, ey, ez, sender_bits}
__device__ float4 g_pack[MAXN * NCH];     // {n1x, n1y, n1z, n0v} per (node, channel)

// One wide pass: histogram+rank atomics, node-feature packing, coords copy.
// Requires g_counts == 0 on entry (true at load; k_scatter re-zeroes each call).
__global__ void k_hist(const int* __restrict__ recv, int E,
                       const float* __restrict__ nodes0,
                       const float* __restrict__ nodes1, int npack,
                       const float* __restrict__ coords, float* __restrict__ outc,
                       int ncoord) {
    int i = blockIdx.x * blockDim.x + threadIdx.x;
    if (i < E) g_rank[i] = atomicAdd(&g_counts[recv[i]], 1);
    if (i < npack)
        g_pack[i] = make_float4(nodes1[3 * i], nodes1[3 * i + 1],
                                nodes1[3 * i + 2], nodes0[i]);
    if (i < ncoord) outc[i] = coords[i];
}

// Single-block scan over PADDED counts (rounded up to multiple of 4).
__global__ void k_scan(int n) {
    const int T = 1024;
    const int ITEMS = 20;
    int tid = threadIdx.x;
    int lane = tid & 31, wid = tid >> 5;
    int start = tid * ITEMS;

    int loc[ITEMS];
    int sum = 0;
    #pragma unroll
    for (int k = 0; k < ITEMS; k++) {
        int i = start + k;
        int v = (i < n) ? g_counts[i] : 0;
        loc[k] = sum;
        sum += (v + 3) & ~3;              // padded size
    }
    int s = sum;
    #pragma unroll
    for (int off = 1; off < 32; off <<= 1) {
        int t = __shfl_up_sync(0xffffffffu, s, off);
        if (lane >= off) s += t;
    }
    __shared__ int wsum[32];
    if (lane == 31) wsum[wid] = s;
    __syncthreads();
    if (wid == 0) {
        int w = wsum[lane];
        #pragma unroll
        for (int off = 1; off < 32; off <<= 1) {
            int t = __shfl_up_sync(0xffffffffu, w, off);
            if (lane >= off) w += t;
        }
        wsum[lane] = w;
    }
    __syncthreads();
    int base = (wid > 0 ? wsum[wid - 1] : 0) + (s - sum);
    #pragma unroll
    for (int k = 0; k < ITEMS; k++) {
        int i = start + k;
        if (i < n) g_row[i] = base + loc[k];
    }
    if (tid == T - 1) g_row[n] = wsum[31];
}

// Scatter + pad fill. Threads [0,E): one scattered 16B store per edge.
// Threads [E, E+n_nodes): fill node pad slots with the zero-contribution
// dummy record (r=40 -> all rbfs == 0) and re-zero g_counts for next call.
__global__ void k_scatter(const int* __restrict__ recv,
                          const int* __restrict__ senders,
                          const float* __restrict__ edges, int E, int n_nodes) {
    int i = blockIdx.x * blockDim.x + threadIdx.x;
    if (i < E) {
        int pos = g_row[recv[i]] + g_rank[i];
        float ex = edges[3 * i + 0];
        float ey = edges[3 * i + 1];
        float ez = edges[3 * i + 2];
        g_rec[pos] = make_float4(ex, ey, ez, __int_as_float(senders[i]));
    } else {
        int j = i - E;
        if (j < n_nodes) {
            int v = g_counts[j];
            g_counts[j] = 0;
            int rowstart = g_row[j];
            int vp = (v + 3) & ~3;
            const float4 DUMMY = make_float4(40.0f, 0.0f, 0.0f, 0.0f);
            for (int d = v; d < vp; d++) g_rec[rowstart + d] = DUMMY;
        }
    }
}

__device__ __forceinline__ float fast_sqrt(float x) {
    float r;
    asm("sqrt.approx.f32 %0, %1;" : "=f"(r) : "f"(x));
    return r;
}

// Radial + tensor-product body for one edge (always unguarded).
#define EDGE_BODY(rec, n0v, n1x, n1y, n1z)                                     \
{                                                                              \
    float ex = (rec).x, ey = (rec).y, ez = (rec).z;                            \
    float r2 = fmaf(ex, ex, fmaf(ey, ey, ez * ez));                            \
    float r  = fast_sqrt(r2);                                                  \
    float E0 = __expf(-0.7f * r2);                                             \
    float tt = __expf(1.225f * r);                                             \
    float q1 = E0 * tt, q2 = q1 * tt, q3 = q2 * tt, q4 = q3 * tt;              \
    float rad00 = fmaf(q4, a00[4], fmaf(q3, a00[3], fmaf(q2, a00[2], fmaf(q1, a00[1], E0 * a00[0])))); \
    float rad01 = fmaf(q4, a01[4], fmaf(q3, a01[3], fmaf(q2, a01[2], fmaf(q1, a01[1], E0 * a01[0])))); \
    float rad10 = fmaf(q4, a10[4], fmaf(q3, a10[3], fmaf(q2, a10[2], fmaf(q1, a10[1], E0 * a10[0])))); \
    float rad11 = fmaf(q4, a11[4], fmaf(q3, a11[3], fmaf(q2, a11[2], fmaf(q1, a11[1], E0 * a11[0])))); \
    m0a = fmaf(n0v, rad00, m0a);                                               \
    float dot11 = fmaf(n1x, ey, fmaf(n1y, ez, n1z * ex));                      \
    m0b = fmaf(W110f * rad11, dot11, m0b);                                     \
    float t01 = (n0v) * rad01;                                                 \
    m1a0 = fmaf(t01, ey, m1a0);                                                \
    m1a1 = fmaf(t01, ez, m1a1);                                                \
    m1a2 = fmaf(t01, ex, m1a2);                                                \
    m1b0 = fmaf(rad10, n1x, m1b0);                                             \
    m1b1 = fmaf(rad10, n1y, m1b1);                                             \
    m1b2 = fmaf(rad10, n1z, m1b2);                                             \
    float t11 = W111f * rad11;                                                 \
    m1c0 = fmaf(t11, (n1y) * ex - (n1z) * ez, m1c0);                           \
    m1c1 = fmaf(t11, (n1z) * ey - (n1x) * ex, m1c1);                           \
    m1c2 = fmaf(t11, (n1x) * ez - (n1y) * ey, m1c2);                           \
}

// Main gather: grid-stride NODE loop per warp; padded segments (no guards).
// R15 structure: rec 1-deep prefetch, pack loads at iteration top.
// Epilogue stores split across both halves (shfl_xor leaves sums in both).
__global__ void __launch_bounds__(256, 4) k_main(
    const float* __restrict__ c00, const float* __restrict__ c01,
    const float* __restrict__ c10, const float* __restrict__ c11,
    const float* __restrict__ w000, const float* __restrict__ w011,
    const float* __restrict__ w101, const float* __restrict__ w110,
    const float* __restrict__ w111,
    float* __restrict__ out0, float* __restrict__ out1, int n_nodes)
{
    int gwarp = (blockIdx.x * blockDim.x + threadIdx.x) >> 5;
    int nwarps = (gridDim.x * blockDim.x) >> 5;
    int lane = threadIdx.x & 31;
    int c = lane & 15;
    int half = lane >> 4;

    const float Kf[NB] = {
        1.0f,
        (float)exp(-0.7 * 0.875 * 0.875),
        (float)exp(-0.7 * 1.75  * 1.75),
        (float)exp(-0.7 * 2.625 * 2.625),
        (float)exp(-0.7 * 3.5   * 3.5)
    };
    const float Y00 = 0.28209479177387814f;
    const float Y1C = 0.4886025119029199f;
    float W000f = w000[c] * Y00;
    float W011f = w011[c] * Y1C;
    float W101f = w101[c] * Y00;
    float W110f = w110[c] * 0.57735026918962576f * Y1C;  // 1/sqrt(3) * Y1C
    float W111f = w111[c] * 0.70710678118654752f * Y1C;  // 1/sqrt(2) * Y1C

    float a00[NB], a01[NB], a10[NB], a11[NB];
    #pragma unroll
    for (int k = 0; k < NB; k++) {
        a00[k] = c00[c * NB + k] * Kf[k] * W000f;   // rad00 pre-weighted
        a01[k] = c01[c * NB + k] * Kf[k] * W011f;   // rad01 pre-weighted
        a10[k] = c10[c * NB + k] * Kf[k] * W101f;   // rad10 pre-weighted
        a11[k] = c11[c * NB + k] * Kf[k];           // rad11 raw (two weights)
    }

    for (int node = gwarp; node < n_nodes; node += nwarps) {
        int rs = g_row[node];
        int re = g_row[node + 1];      // padded: (re - rs) % 4 == 0

        float m0a = 0.f, m0b = 0.f;
        float m1a0 = 0.f, m1a1 = 0.f, m1a2 = 0.f;
        float m1b0 = 0.f, m1b1 = 0.f, m1b2 = 0.f;
        float m1c0 = 0.f, m1c1 = 0.f, m1c2 = 0.f;

        if (rs < re) {
            // Pipeline prologue (segment length >= 4, no clamps needed).
            float4 rec0 = g_rec[rs + half];
            float4 rec1 = g_rec[rs + 2 + half];

            #pragma unroll 1
            for (int base = rs; base < re; base += 4) {
                // Node gathers: ONE 16B load per edge (senders already in regs).
                int s0 = __float_as_int(rec0.w);
                int s1 = __float_as_int(rec1.w);
                float4 pk0 = g_pack[s0 * NCH + c];
                float4 pk1 = g_pack[s1 * NCH + c];

                // Prefetch NEXT group's recs (may overrun into slack — fine).
                float4 nrec0 = g_rec[base + 4 + half];
                float4 nrec1 = g_rec[base + 6 + half];

                EDGE_BODY(rec0, pk0.w, pk0.x, pk0.y, pk0.z);
                EDGE_BODY(rec1, pk1.w, pk1.x, pk1.y, pk1.z);

                rec0 = nrec0; rec1 = nrec1;
            }
        }

        // Combine the two half-warps (sums land in BOTH halves).
        const unsigned FULL = 0xffffffffu;
        m0a  += __shfl_xor_sync(FULL, m0a, 16);
        m0b  += __shfl_xor_sync(FULL, m0b, 16);
        m1a0 += __shfl_xor_sync(FULL, m1a0, 16);
        m1a1 += __shfl_xor_sync(FULL, m1a1, 16);
        m1a2 += __shfl_xor_sync(FULL, m1a2, 16);
        m1b0 += __shfl_xor_sync(FULL, m1b0, 16);
        m1b1 += __shfl_xor_sync(FULL, m1b1, 16);
        m1b2 += __shfl_xor_sync(FULL, m1b2, 16);
        m1c0 += __shfl_xor_sync(FULL, m1c0, 16);
        m1c1 += __shfl_xor_sync(FULL, m1c1, 16);
        m1c2 += __shfl_xor_sync(FULL, m1c2, 16);

        // Epilogue split: half 0 stores out0 + m1a, half 1 stores m1b + m1c.
        if (half == 0) {
            out0[node * 32 + c]      = m0a;
            out0[node * 32 + 16 + c] = m0b;
            float* oa = out1 + (node * 48 + c) * 3;
            oa[0] = m1a0; oa[1] = m1a1; oa[2] = m1a2;
        } else {
            float* ob = out1 + (node * 48 + 16 + c) * 3;
            ob[0] = m1b0; ob[1] = m1b1; ob[2] = m1b2;
            float* oc = out1 + (node * 48 + 32 + c) * 3;
            oc[0] = m1c0; oc[1] = m1c1; oc[2] = m1c2;
        }
    }
}

extern "C" void kernel_launch(void* const* d_in, const int* in_sizes, int n_in,
                              void* d_out, int out_size) {
    const float* coords  = (const float*)d_in[0];
    const float* nodes0  = (const float*)d_in[1];
    const float* nodes1  = (const float*)d_in[2];
    const float* edges   = (const float*)d_in[3];
    const int*   senders = (const int*)d_in[4];
    const int*   recv    = (const int*)d_in[5];
    const float* c00 = (const float*)d_in[6];
    const float* c01 = (const float*)d_in[7];
    const float* c10 = (const float*)d_in[8];
    const float* c11 = (const float*)d_in[9];
    const float* w000 = (const float*)d_in[10];
    const float* w011 = (const float*)d_in[11];
    const float* w101 = (const float*)d_in[12];
    const float* w110 = (const float*)d_in[13];
    const float* w111 = (const float*)d_in[14];
    float* out = (float*)d_out;

    int N = in_sizes[0] / 3;
    int E = in_sizes[3] / 3;

    float* out0 = out + (size_t)3 * N;
    float* out1 = out0 + (size_t)32 * N;

    // hist + node packing + coords copy fused.
    k_hist<<<(E + 255) / 256, 256>>>(recv, E, nodes0, nodes1, N * NCH,
                                     coords, out, 3 * N);
    k_scan<<<1, 1024>>>(N);
    // scatter + pad fill (E edge threads + N fill threads).
    k_scatter<<<(E + N + 255) / 256, 256>>>(recv, senders, edges, E, N);
    // Full-residency grid: 592 blocks x 8 warps = 4736 warps.
    k_main<<<592, 256>>>(c00, c01, c10, c11,
                         w000, w011, w101, w110, w111,
                         out0, out1, N);
}